// round 10
// baseline (speedup 1.0000x reference)
#include <cuda_runtime.h>
#include <cuda_fp16.h>
#include <cstdint>

// BarycentricInterpolator: out[b, m] = sum_k f[b, tri[m,k]] * w[m,k]
// B=128, N=10000, M=500000.
//
// R10 = R9 resubmission (infra failure, never measured), restructured:
// lane-interleaved m mapping (m = mb + k*bd + tid) so record LDG.128 and
// output STG.32 are fully coalesced. L1 wavefronts/warp-iter ~173 -> ~77.
// Tile/fill/math identical to R8 (100.4us, L1=88.7% binding).

#define BB 4
#define MAX_M 600000

__device__ __align__(16) uint4 g_recs[MAX_M];
// record: x = i0 | i1<<16 ; y = i2 | h(w2)<<16 ; z = h2(w0,w0) ; w = h2(w1,w1)

__global__ void pack_kernel(const int* __restrict__ tri,
                            const float* __restrict__ w,
                            int M) {
    int m = blockIdx.x * blockDim.x + threadIdx.x;
    if (m >= M) return;
    unsigned i0 = (unsigned)tri[3 * m + 0];
    unsigned i1 = (unsigned)tri[3 * m + 1];
    unsigned i2 = (unsigned)tri[3 * m + 2];
    float w0 = w[3 * m + 0];
    float w1 = w[3 * m + 1];
    float w2 = 1.0f - w0 - w1;
    unsigned h0 = (unsigned)__half_as_ushort(__float2half_rn(w0));
    unsigned h1 = (unsigned)__half_as_ushort(__float2half_rn(w1));
    unsigned h2 = (unsigned)__half_as_ushort(__float2half_rn(w2));
    uint4 r;
    r.x = (i0 & 0xFFFFu) | (i1 << 16);
    r.y = (i2 & 0xFFFFu) | (h2 << 16);
    r.z = h0 | (h0 << 16);
    r.w = h1 | (h1 << 16);
    g_recs[m] = r;
}

__device__ __forceinline__ __half2 u2h(unsigned u) {
    return *reinterpret_cast<__half2*>(&u);
}

__device__ __forceinline__ unsigned packh2(float a, float b) {
    __half2 h = __floats2half2_rn(a, b);   // .x = a (low), .y = b (high)
    return *reinterpret_cast<unsigned*>(&h);
}

__global__ void __launch_bounds__(768, 2)
interp_kernel(const float* __restrict__ f,
              float* __restrict__ out,
              int Bv, int Nv, int Mv) {
    extern __shared__ __half fsh[];                 // BB * Nv halves, fsh[i*4 + bl]
    const uint2* __restrict__ fs2 = reinterpret_cast<const uint2*>(fsh);

    const int NB = Bv / BB;                         // 32 b-groups
    const long long J = (long long)NB * (long long)Mv;

    long long j0 = (long long)blockIdx.x * J / gridDim.x;
    long long j1 = (long long)(blockIdx.x + 1) * J / gridDim.x;

    long long j = j0;
    while (j < j1) {
        const int gb = (int)(j / Mv);
        const long long seg_end = min(j1, (long long)(gb + 1) * (long long)Mv);

        // ---- stage BB rows of f into smem as fp16, interleaved [i*4 + bl] ----
        {
            const float* frow = f + (long long)gb * BB * Nv;
            if ((Nv & 3) == 0) {
                const float4* r0 = reinterpret_cast<const float4*>(frow);
                const float4* r1 = reinterpret_cast<const float4*>(frow + Nv);
                const float4* r2 = reinterpret_cast<const float4*>(frow + 2 * Nv);
                const float4* r3 = reinterpret_cast<const float4*>(frow + 3 * Nv);
                uint4* dst = reinterpret_cast<uint4*>(fsh);   // 2 columns per uint4
                const int nq = Nv >> 2;
                for (int q = threadIdx.x; q < nq; q += blockDim.x) {
                    float4 a = r0[q], b = r1[q], c = r2[q], d = r3[q];
                    uint4 u0, u1;
                    u0.x = packh2(a.x, b.x); u0.y = packh2(c.x, d.x);
                    u0.z = packh2(a.y, b.y); u0.w = packh2(c.y, d.y);
                    u1.x = packh2(a.z, b.z); u1.y = packh2(c.z, d.z);
                    u1.z = packh2(a.w, b.w); u1.w = packh2(c.w, d.w);
                    dst[2 * q]     = u0;
                    dst[2 * q + 1] = u1;
                }
            } else {
                const int tot = BB * Nv;
                for (int t = threadIdx.x; t < tot; t += blockDim.x) {
                    int bl = t / Nv;
                    int i  = t - bl * Nv;
                    fsh[i * BB + bl] = __float2half_rn(frow[(long long)bl * Nv + i]);
                }
            }
        }
        __syncthreads();

        const int m_lo = (int)(j - (long long)gb * Mv);
        const int m_hi = (int)(seg_end - (long long)gb * Mv);
        float* __restrict__ outb = out + (long long)gb * BB * Mv;

        const int bd = (int)blockDim.x;
        const int step = 4 * bd;

        // lane-interleaved mapping: thread handles mb + k*bd + tid, k = 0..3
        for (int mb = m_lo; mb < m_hi; mb += step) {
            int mk[4];
            bool pk[4];
            uint4 rk[4];
            #pragma unroll
            for (int k = 0; k < 4; k++) {
                mk[k] = mb + k * bd + (int)threadIdx.x;
                pk[k] = mk[k] < m_hi;
                if (pk[k]) rk[k] = __ldcg(&g_recs[mk[k]]);
            }
            #pragma unroll
            for (int k = 0; k < 4; k++) {
                if (!pk[k]) continue;
                const uint4 r = rk[k];
                const int i0 = r.x & 0xFFFFu;
                const int i1 = r.x >> 16;
                const int i2 = r.y & 0xFFFFu;
                const __half2 w0 = u2h(r.z);
                const __half2 w1 = u2h(r.w);
                const __half2 w2 =
                    __half2half2(__ushort_as_half((unsigned short)(r.y >> 16)));
                uint2 va = fs2[i0];
                uint2 vb = fs2[i1];
                uint2 vc = fs2[i2];
                __half2 sA = __hfma2(w0, u2h(va.x),
                             __hfma2(w1, u2h(vb.x), __hmul2(w2, u2h(vc.x))));
                __half2 sB = __hfma2(w0, u2h(va.y),
                             __hfma2(w1, u2h(vb.y), __hmul2(w2, u2h(vc.y))));
                float* o = outb + mk[k];
                __stcs(o,                     __low2float(sA));
                __stcs(o + Mv,                __high2float(sA));
                __stcs(o + 2 * (long long)Mv, __low2float(sB));
                __stcs(o + 3 * (long long)Mv, __high2float(sB));
            }
        }
        __syncthreads();
        j = seg_end;
    }
}

// Exact-fp32 fallback for shapes the fast path can't handle.
__global__ void naive_kernel(const float* __restrict__ f,
                             const int* __restrict__ tri,
                             const float* __restrict__ w,
                             float* __restrict__ out,
                             int B, int N, int M) {
    int m = blockIdx.x * blockDim.x + threadIdx.x;
    if (m >= M) return;
    int i0 = tri[3 * m], i1 = tri[3 * m + 1], i2 = tri[3 * m + 2];
    float w0 = w[3 * m], w1 = w[3 * m + 1], w2 = w[3 * m + 2];
    for (int b = 0; b < B; b++) {
        out[(long long)b * M + m] =
            w0 * f[(long long)b * N + i0] +
            w1 * f[(long long)b * N + i1] +
            w2 * f[(long long)b * N + i2];
    }
}

extern "C" void kernel_launch(void* const* d_in, const int* in_sizes, int n_in,
                              void* d_out, int out_size) {
    const float* f   = (const float*)d_in[0];
    const int*   tri = (const int*)d_in[1];
    const float* w   = (const float*)d_in[2];
    float* out = (float*)d_out;

    const int M = in_sizes[1] / 3;
    const int B = out_size / M;
    const int N = in_sizes[0] / B;

    const bool fast = (B % BB == 0) && (N <= 14000) && (M <= MAX_M);

    if (!fast) {
        naive_kernel<<<(M + 255) / 256, 256>>>(f, tri, w, out, B, N, M);
        return;
    }

    pack_kernel<<<(M + 255) / 256, 256>>>(tri, w, M);

    int sms = 148;
    cudaDeviceGetAttribute(&sms, cudaDevAttrMultiProcessorCount, 0);

    const int smem_bytes = BB * N * (int)sizeof(__half);   // 80 KB at N=10000
    cudaFuncSetAttribute(interp_kernel,
                         cudaFuncAttributeMaxDynamicSharedMemorySize, smem_bytes);

    const int grid = 2 * sms;   // 2 blocks resident per SM, single wave
    interp_kernel<<<grid, 768, smem_bytes>>>(f, out, B, N, M);
}